// round 17
// baseline (speedup 1.0000x reference)
#include <cuda_runtime.h>
#include <cuda_bf16.h>
#include <cstdint>
#define HDIM 512
#define BATCH 256
#define TLEN 512
#define NSTEPS 511
#define FC1_N 1024
#define FC2_N 32000
typedef unsigned long long u64;

// -------- persistent device scratch --------
__device__ uint2 g_wf[32 * 512 * 32];      // 4MB W B-fragments [kx][ks*16+nt*2+hl][lane]
__device__ uint4 g_ha[2][2][4][32][4][32]; // 2MB h A-fragments [buf][hl][by][ks][mt][lane]
__device__ float g_hlast[BATCH * HDIM];
__device__ float g_z[BATCH * FC1_N];
__device__ unsigned int g_flag[128];       // [by][kx]
__device__ int g_dummy;

__device__ __forceinline__ u64 pack2(float lo, float hi) {
    u64 r; asm("mov.b64 %0, {%1, %2};" : "=l"(r) : "f"(lo), "f"(hi)); return r;
}
__device__ __forceinline__ void unpack2(u64 v, float& lo, float& hi) {
    asm("mov.b64 {%0, %1}, %2;" : "=f"(lo), "=f"(hi) : "l"(v));
}
__device__ __forceinline__ void ffma2(u64& d, u64 a, u64 b) {
    asm("fma.rn.f32x2 %0, %1, %2, %0;" : "+l"(d) : "l"(a), "l"(b));
}
__device__ __forceinline__ uint4 ldcg4(const void* p) {
    uint4 v;
    asm volatile("ld.global.cg.v4.b32 {%0,%1,%2,%3}, [%4];"
                 : "=r"(v.x), "=r"(v.y), "=r"(v.z), "=r"(v.w) : "l"(p));
    return v;
}
__device__ __forceinline__ void stcg4(void* p, uint4 v) {
    asm volatile("st.global.cg.v4.b32 [%0], {%1,%2,%3,%4};"
                 :: "l"(p), "r"(v.x), "r"(v.y), "r"(v.z), "r"(v.w) : "memory");
}
__device__ __forceinline__ unsigned int ld_acq(const unsigned int* p) {
    unsigned int v;
    asm volatile("ld.global.acquire.gpu.b32 %0, [%1];" : "=r"(v) : "l"(p));
    return v;
}
__device__ __forceinline__ void st_rel(unsigned int* p, unsigned int v) {
    asm volatile("st.global.release.gpu.b32 [%0], %1;" :: "l"(p), "r"(v) : "memory");
}
__device__ __forceinline__ float sigmoidf_(float x) { return 1.0f / (1.0f + __expf(-x)); }
__device__ __forceinline__ float tanhf_(float x) { return 1.0f - 2.0f / (__expf(2.0f * x) + 1.0f); }
__device__ __forceinline__ unsigned short bfhi(float v) {
    return __bfloat16_as_ushort(__float2bfloat16(v));
}
__device__ __forceinline__ unsigned short bflo(float v) {
    __nv_bfloat16 h = __float2bfloat16(v);
    return __bfloat16_as_ushort(__float2bfloat16(v - __bfloat162float(h)));
}
// warp MMA: D[16m][8n] += A[16m][16k](bf16,row) * B[16k][8n](bf16,col), f32 acc
__device__ __forceinline__ void mma_bf16(float* d, const uint4& A, const uint2& B) {
    asm volatile("mma.sync.aligned.m16n8k16.row.col.f32.bf16.bf16.f32 "
                 "{%0,%1,%2,%3}, {%4,%5,%6,%7}, {%8,%9}, {%0,%1,%2,%3};"
                 : "+f"(d[0]), "+f"(d[1]), "+f"(d[2]), "+f"(d[3])
                 : "r"(A.x), "r"(A.y), "r"(A.z), "r"(A.w), "r"(B.x), "r"(B.y));
}

// ---- W -> B-fragment images (hi/lo split), R16-proven ----
__global__ void prep_wf(const float* __restrict__ w) {
    int tid = blockIdx.x * blockDim.x + threadIdx.x;   // 0..524287
    int lane = tid & 31, q = tid >> 5;
    int hl = q & 1, nt = (q >> 1) & 7, ks = (q >> 4) & 31, kx = q >> 9;
    int g = lane >> 2, tc = lane & 3;
    int gate = nt >> 1, j = (nt & 1) * 8 + g;
    const float* row = w + (size_t)(gate * HDIM + kx * 16 + j) * HDIM;
    int k0 = ks * 16 + tc * 2;
    float v00 = row[k0], v01 = row[k0 + 1], v10 = row[k0 + 8], v11 = row[k0 + 9];
    unsigned short b00 = hl ? bflo(v00) : bfhi(v00);
    unsigned short b01 = hl ? bflo(v01) : bfhi(v01);
    unsigned short b10 = hl ? bflo(v10) : bfhi(v10);
    unsigned short b11 = hl ? bflo(v11) : bfhi(v11);
    uint2 r;
    r.x = (unsigned)b00 | ((unsigned)b01 << 16);
    r.y = (unsigned)b10 | ((unsigned)b11 << 16);
    g_wf[tid] = r;
}

__global__ void prep_misc() {
    int i = blockIdx.x * blockDim.x + threadIdx.x;
    int n = gridDim.x * blockDim.x;
    uint4 z = make_uint4(0, 0, 0, 0);
    uint4* ha = &g_ha[0][0][0][0][0][0];
    for (int j = i; j < 2 * 2 * 4 * 32 * 4 * 32; j += n) ha[j] = z;
    if (i < 128) g_flag[i] = 0u;
}

// spacer: puts lstm_mma at launch #4 (the ncu capture slot)
__global__ void nopk(int v) { if (v == 12345) g_dummy = v; }

// ============================================================================
// Persistent HMMA LSTM, 256 threads (2 warps/SMSP).
// 128 CTAs (32 kx x 4 by), 1 CTA/SM. CTA: D[64 batch][64 n], K=512.
// Warp w: gate = w>>1, m-half mh = w&1 -> 2 n-tiles x 2 m-tiles, 12 MMAs/kstep
// (3 split terms: hh + lh + hl). W resident in smem as B-fragments (128kB).
// h via global A-fragment images (.cg), chunk(4 kstep)-double-buffered in smem.
// Pointwise/cst/h-store on threads 0..127 (R16-proven mapping).
// ============================================================================
#define SM_A  131072
#define SM_D  163840
#define SM_BW 180736
#define SMEMB 181248
__global__ __launch_bounds__(256, 1)
void lstm_mma(const int* __restrict__ trg,
              const float* __restrict__ w_ih,
              const float* __restrict__ b_ih,
              const float* __restrict__ b_hh)
{
    extern __shared__ char sm[];
    uint2* sWB = (uint2*)sm;                  // [512][32] fragments
    uint4* sA  = (uint4*)(sm + SM_A);         // [2 buf][4ksl*4mt*2hl][32 lane]
    float* sD  = (float*)(sm + SM_D);         // [64 m][66 pitch]
    float* sbw = (float*)(sm + SM_BW);        // [64 bias | 64 wih]

    const int t = threadIdx.x;
    const int kx = blockIdx.x & 31, by = blockIdx.x >> 5;
    const int b0 = by * 64;
    const int w = t >> 5, lane = t & 31;
    const int g = lane >> 2, tc = lane & 3;
    const int gate = w >> 1, mh = w & 1;      // warp tile: gate, m-half

    // load W fragment slice (16384 uint2 = 128kB), coalesced
    {
        const uint2* ws = g_wf + (size_t)kx * 16384;
        for (int i = t; i < 16384; i += 256) sWB[i] = ws[i];
    }
    if (t < 64) {
        int gg = t >> 4, j = t & 15;
        int row = gg * HDIM + kx * 16 + j;
        sbw[t]      = b_ih[row] + b_hh[row];
        sbw[64 + t] = w_ih[row];
    }
    float cst[2][4];
#pragma unroll
    for (int a = 0; a < 2; a++)
#pragma unroll
        for (int bq = 0; bq < 4; bq++) cst[a][bq] = 0.0f;
    __syncthreads();

#pragma unroll 1
    for (int s = 0; s < NSTEPS; s++) {
        // entry gate: all 32 producers of my by-group finished step s-1
        if (s > 0) {
            if (t < 32) { while (ld_acq(&g_flag[by * 32 + t]) < (unsigned)s) { } }
            __syncthreads();
        }

        float acc[2][2][4];   // [ntl][m-local][reg]
#pragma unroll
        for (int a = 0; a < 2; a++)
#pragma unroll
            for (int m = 0; m < 2; m++)
#pragma unroll
                for (int r = 0; r < 4; r++) acc[a][m][r] = 0.0f;

        uint4 pf[4];
#define LDG_CHUNK(c) do {                                                     \
        _Pragma("unroll")                                                     \
        for (int q = 0; q < 4; q++) {                                         \
            int fl = q * 256 + t;                                             \
            int l2 = fl & 31, hl = (fl >> 5) & 1, mq = (fl >> 6) & 3,         \
                kl = fl >> 8;                                                 \
            pf[q] = ldcg4(&g_ha[s & 1][hl][by][(c) * 4 + kl][mq][l2]);        \
        } } while (0)
#define STS_CHUNK(buf) do {                                                   \
        _Pragma("unroll")                                                     \
        for (int q = 0; q < 4; q++) {                                         \
            int fl = q * 256 + t;                                             \
            int l2 = fl & 31, hl = (fl >> 5) & 1, mq = (fl >> 6) & 3,         \
                kl = fl >> 8;                                                 \
            sA[(buf) * 1024 + ((kl * 4 + mq) * 2 + hl) * 32 + l2] = pf[q];    \
        } } while (0)

        LDG_CHUNK(0);
        STS_CHUNK(0);
        __syncthreads();

#pragma unroll 1
        for (int c = 0; c < 8; c++) {
            if (c < 7) LDG_CHUNK(c + 1);
            const uint4* Ab = sA + (c & 1) * 1024;
#pragma unroll
            for (int kl = 0; kl < 4; kl++) {
                int ks = c * 4 + kl;
                uint4 ah[2], al[2];
#pragma unroll
                for (int m = 0; m < 2; m++) {
                    int mt = mh * 2 + m;
                    ah[m] = Ab[((kl * 4 + mt) * 2 + 0) * 32 + lane];
                    al[m] = Ab[((kl * 4 + mt) * 2 + 1) * 32 + lane];
                }
                uint2 bh[2], bl[2];
#pragma unroll
                for (int nl = 0; nl < 2; nl++) {
                    int nt = gate * 2 + nl;
                    bh[nl] = sWB[(ks * 16 + nt * 2 + 0) * 32 + lane];
                    bl[nl] = sWB[(ks * 16 + nt * 2 + 1) * 32 + lane];
                }
#pragma unroll
                for (int nl = 0; nl < 2; nl++)
#pragma unroll
                    for (int m = 0; m < 2; m++) {
                        mma_bf16(acc[nl][m], ah[m], bh[nl]);
                        mma_bf16(acc[nl][m], al[m], bh[nl]);
                        mma_bf16(acc[nl][m], ah[m], bl[nl]);
                    }
            }
            if (c < 7) STS_CHUNK((c + 1) & 1);
            __syncthreads();
        }

        // ---- D exchange: acc fragments -> sD[m][n] (pitch 66) ----
#pragma unroll
        for (int nl = 0; nl < 2; nl++)
#pragma unroll
            for (int m = 0; m < 2; m++) {
                int n0 = gate * 16 + nl * 8 + 2 * tc;
                int mm = (mh * 2 + m) * 16 + g;
                *(float2*)&sD[mm * 66 + n0] =
                    make_float2(acc[nl][m][0], acc[nl][m][1]);
                *(float2*)&sD[(mm + 8) * 66 + n0] =
                    make_float2(acc[nl][m][2], acc[nl][m][3]);
            }
        __syncthreads();

        // ---- pointwise on threads 0..127 (R16-proven mapping) ----
        if (t < 128) {
            const int mt = t >> 5;
            float hv[2][4];
#pragma unroll
            for (int rr = 0; rr < 2; rr++) {
                int m = mt * 16 + g + rr * 8;
                float x = (float)__ldg(trg + (size_t)(b0 + m) * TLEN + s);
#pragma unroll
                for (int jj = 0; jj < 4; jj++) {
                    int j = 2 * tc + (jj & 1) + (jj >> 1) * 8;
                    float gi = sD[m * 66 + 0 * 16 + j] + sbw[0 * 16 + j] + x * sbw[64 + 0 * 16 + j];
                    float gf = sD[m * 66 + 1 * 16 + j] + sbw[1 * 16 + j] + x * sbw[64 + 1 * 16 + j];
                    float gg = sD[m * 66 + 2 * 16 + j] + sbw[2 * 16 + j] + x * sbw[64 + 2 * 16 + j];
                    float go = sD[m * 66 + 3 * 16 + j] + sbw[3 * 16 + j] + x * sbw[64 + 3 * 16 + j];
                    float iv = sigmoidf_(gi), fv = sigmoidf_(gf);
                    float gv = tanhf_(gg),   ov = sigmoidf_(go);
                    float cn = fmaf(fv, cst[rr][jj], iv * gv);
                    cst[rr][jj] = cn;
                    hv[rr][jj] = ov * tanhf_(cn);
                }
            }
            uint4 hi4, lo4;
            hi4.x = (unsigned)bfhi(hv[0][0]) | ((unsigned)bfhi(hv[0][1]) << 16);
            hi4.y = (unsigned)bfhi(hv[1][0]) | ((unsigned)bfhi(hv[1][1]) << 16);
            hi4.z = (unsigned)bfhi(hv[0][2]) | ((unsigned)bfhi(hv[0][3]) << 16);
            hi4.w = (unsigned)bfhi(hv[1][2]) | ((unsigned)bfhi(hv[1][3]) << 16);
            lo4.x = (unsigned)bflo(hv[0][0]) | ((unsigned)bflo(hv[0][1]) << 16);
            lo4.y = (unsigned)bflo(hv[1][0]) | ((unsigned)bflo(hv[1][1]) << 16);
            lo4.z = (unsigned)bflo(hv[0][2]) | ((unsigned)bflo(hv[0][3]) << 16);
            lo4.w = (unsigned)bflo(hv[1][2]) | ((unsigned)bflo(hv[1][3]) << 16);
            stcg4(&g_ha[(s & 1) ^ 1][0][by][kx][mt][lane], hi4);
            stcg4(&g_ha[(s & 1) ^ 1][1][by][kx][mt][lane], lo4);
            if (s == NSTEPS - 1) {
#pragma unroll
                for (int rr = 0; rr < 2; rr++)
#pragma unroll
                    for (int jj = 0; jj < 4; jj++) {
                        int j = 2 * tc + (jj & 1) + (jj >> 1) * 8;
                        int b = b0 + mt * 16 + g + rr * 8;
                        g_hlast[(size_t)b * HDIM + kx * 16 + j] = hv[rr][jj];
                    }
            }
        }

        if (s < NSTEPS - 1) {
            __syncthreads();
            if (t == 0) {
                __threadfence();
                st_rel(&g_flag[by * 32 + kx], (unsigned)(s + 1));
            }
        }
    }
}

// ============================================================================
// fc1 head (R3-proven): C = A @ W^T + bias, ReLU.
// ============================================================================
__global__ __launch_bounds__(256)
void fc_gemm(int asel, const float* __restrict__ W, const float* __restrict__ bias,
             float* __restrict__ C, int K, int N, int do_relu)
{
    __shared__ float  sW[32 * 128];
    __shared__ float2 sH2[32 * 33];
    const float* __restrict__ A = (asel == 0) ? &g_hlast[0] : &g_z[0];
    const int t = threadIdx.x, n0 = blockIdx.x * 128, m0 = blockIdx.y * 32;
    const int cc = t & 15, bi0 = (t >> 4) * 2;

    u64 acc[2][4];
#pragma unroll
    for (int g = 0; g < 4; g++) {
        float2 b2 = *(const float2*)(bias + n0 + g * 32 + 2 * cc);
        acc[0][g] = pack2(b2.x, b2.y);
        acc[1][g] = pack2(b2.x, b2.y);
    }
    const int r128 = t >> 1, hf = t & 1;
    const float4* __restrict__ Wrow = (const float4*)(W + (size_t)(n0 + r128) * K);
    const int hbi = t >> 3, hk0 = (t & 7) * 4;
    const u64* sWu = (const u64*)sW;
    const u64* sHu = (const u64*)sH2;

    for (int kc = 0; kc < K; kc += 32) {
        if (kc) __syncthreads();
#pragma unroll
        for (int q = 0; q < 4; q++) {
            float4 v = Wrow[(kc + hf * 16) / 4 + q];
            int kl = hf * 16 + q * 4;
            sW[(kl + 0) * 128 + r128] = v.x;
            sW[(kl + 1) * 128 + r128] = v.y;
            sW[(kl + 2) * 128 + r128] = v.z;
            sW[(kl + 3) * 128 + r128] = v.w;
        }
        float4 hv = *(const float4*)(A + (size_t)(m0 + hbi) * K + kc + hk0);
        sH2[(hk0 + 0) * 33 + hbi] = make_float2(hv.x, hv.x);
        sH2[(hk0 + 1) * 33 + hbi] = make_float2(hv.y, hv.y);
        sH2[(hk0 + 2) * 33 + hbi] = make_float2(hv.z, hv.z);
        sH2[(hk0 + 3) * 33 + hbi] = make_float2(hv.w, hv.w);
        __syncthreads();
#pragma unroll 8
        for (int kk = 0; kk < 32; kk++) {
            u64 h0 = sHu[kk * 33 + bi0];
            u64 h1 = sHu[kk * 33 + bi0 + 1];
#pragma unroll
            for (int g = 0; g < 4; g++) {
                u64 w = sWu[kk * 64 + g * 16 + cc];
                ffma2(acc[0][g], w, h0);
                ffma2(acc[1][g], w, h1);
            }
        }
    }
#pragma unroll
    for (int bb = 0; bb < 2; bb++) {
        int m = m0 + bi0 + bb;
#pragma unroll
        for (int g = 0; g < 4; g++) {
            float lo, hi;
            unpack2(acc[bb][g], lo, hi);
            if (do_relu) { lo = fmaxf(lo, 0.0f); hi = fmaxf(hi, 0.0f); }
            *(float2*)(C + (size_t)m * N + n0 + g * 32 + 2 * cc) = make_float2(lo, hi);
        }
    }
}

// ============================================================================
// fc2 head (R10-proven): 1.5 B/MAC tile, grid (250, 8), 128 thr.
// ============================================================================
__global__ __launch_bounds__(128)
void fc2_gemm(const float* __restrict__ W, const float* __restrict__ bias,
              float* __restrict__ C)
{
    __shared__ __align__(16) float sWn[32 * 132];
    __shared__ __align__(16) float sHm[32 * 34];
    const int t = threadIdx.x;
    const int n0 = blockIdx.x * 128, m0 = blockIdx.y * 32;
    const int tn = t & 31, tm = t >> 5;
    const int nb = tn * 4;
    const int kt = t & 7, rr = t >> 3;

    u64 acc[4][4];
    {
        float4 bv = *(const float4*)(bias + n0 + nb);
        u64 b0 = pack2(bv.x, bv.x), b1 = pack2(bv.y, bv.y);
        u64 b2 = pack2(bv.z, bv.z), b3 = pack2(bv.w, bv.w);
#pragma unroll
        for (int j = 0; j < 4; j++) {
            acc[0][j] = b0; acc[1][j] = b1; acc[2][j] = b2; acc[3][j] = b3;
        }
    }

#pragma unroll 1
    for (int kc = 0; kc < 32; kc++) {
        __syncthreads();
#pragma unroll
        for (int p = 0; p < 8; p++) {
            int n = rr + p * 16;
            float4 v = *(const float4*)(W + (size_t)(n0 + n) * 1024 + kc * 32 + kt * 4);
            sWn[(kt * 4 + 0) * 132 + n] = v.x;
            sWn[(kt * 4 + 1) * 132 + n] = v.y;
            sWn[(kt * 4 + 2) * 132 + n] = v.z;
            sWn[(kt * 4 + 3) * 132 + n] = v.w;
        }
#pragma unroll
        for (int p = 0; p < 2; p++) {
            int m = rr + p * 16;
            float4 v = *(const float4*)(g_z + (size_t)(m0 + m) * 1024 + kc * 32 + kt * 4);
            sHm[(kt * 4 + 0) * 34 + m] = v.x;
            sHm[(kt * 4 + 1) * 34 + m] = v.y;
            sHm[(kt * 4 + 2) * 34 + m] = v.z;
            sHm[(kt * 4 + 3) * 34 + m] = v.w;
        }
        __syncthreads();
#pragma unroll
        for (int kk = 0; kk < 32; kk++) {
            float4 wv = *(const float4*)(sWn + kk * 132 + nb);
            u64 h0 = *(const u64*)(sHm + kk * 34 + 2 * tm);
            u64 h1 = *(const u64*)(sHm + kk * 34 + 2 * (tm + 4));
            u64 h2 = *(const u64*)(sHm + kk * 34 + 2 * (tm + 8));
            u64 h3 = *(const u64*)(sHm + kk * 34 + 2 * (tm + 12));
            u64 w0 = pack2(wv.x, wv.x), w1 = pack2(wv.y, wv.y);
            u64 w2 = pack2(wv.z, wv.z), w3 = pack2(wv.w, wv.w);
            ffma2(acc[0][0], w0, h0); ffma2(acc[1][0], w1, h0);
            ffma2(acc[2][0], w2, h0); ffma2(acc[3][0], w3, h0);
            ffma2(acc[0][1], w0, h1); ffma2(acc[1][1], w1, h1);
            ffma2(acc[2][1], w2, h1); ffma2(acc[3][1], w3, h1);
            ffma2(acc[0][2], w0, h2); ffma2(acc[1][2], w1, h2);
            ffma2(acc[2][2], w2, h2); ffma2(acc[3][2], w3, h2);
            ffma2(acc[0][3], w0, h3); ffma2(acc[1][3], w1, h3);
            ffma2(acc[2][3], w2, h3); ffma2(acc[3][3], w3, h3);
        }
    }
#pragma unroll
    for (int j = 0; j < 4; j++) {
        int m = m0 + 2 * (tm + 4 * j);
        float l0, h0, l1, h1, l2, h2, l3, h3;
        unpack2(acc[0][j], l0, h0); unpack2(acc[1][j], l1, h1);
        unpack2(acc[2][j], l2, h2); unpack2(acc[3][j], l3, h3);
        *(float4*)(C + (size_t)m * FC2_N + n0 + nb)       = make_float4(l0, l1, l2, l3);
        *(float4*)(C + (size_t)(m + 1) * FC2_N + n0 + nb) = make_float4(h0, h1, h2, h3);
    }
}

// ============================================================================
extern "C" void kernel_launch(void* const* d_in, const int* in_sizes, int n_in,
                              void* d_out, int out_size) {
    const int*   trg   = (const int*)  d_in[2];
    const float* w_ih  = (const float*)d_in[3];
    const float* w_hh  = (const float*)d_in[4];
    const float* b_ih  = (const float*)d_in[5];
    const float* b_hh  = (const float*)d_in[6];
    const float* fc1_w = (const float*)d_in[7];
    const float* fc1_b = (const float*)d_in[8];
    const float* fc2_w = (const float*)d_in[9];
    const float* fc2_b = (const float*)d_in[10];
    float* out = (float*)d_out;

    cudaFuncSetAttribute(lstm_mma,
                         cudaFuncAttributeMaxDynamicSharedMemorySize, SMEMB);

    prep_wf<<<2048, 256>>>(w_hh);                         // launch 1
    prep_misc<<<256, 256>>>();                            // launch 2
    nopk<<<1, 32>>>(0);                                   // launch 3 (spacer)

    lstm_mma<<<128, 256, SMEMB>>>(trg, w_ih, b_ih, b_hh); // launch 4 = ncu slot

    void* zsym = nullptr;
    cudaGetSymbolAddress(&zsym, g_z);
    float* zptr = (float*)zsym;
    fc_gemm<<<dim3(FC1_N / 128, BATCH / 32), 256>>>(0, fc1_w, fc1_b, zptr, HDIM, FC1_N, 1);
    fc2_gemm<<<dim3(FC2_N / 128, BATCH / 32), 128>>>(fc2_w, fc2_b, out);
}